// round 3
// baseline (speedup 1.0000x reference)
#include <cuda_runtime.h>
#include <cuda_bf16.h>
#include <cstdint>
#include <math.h>

// ---------------- problem constants ----------------
#define BATCH   32
#define SEQ     1024
#define CH      384          // C == H == 384
#define KSZ     3
#define KTOT    (KSZ*CH)     // 1152
#define MAXOUT  3072
#define ROWS    (BATCH*SEQ)  // 32768

// GEMM tiling
#define TM      128
#define KC      32
#define NITER   (KTOT/KC)    // 36
#define APAD    40           // halves per A smem row (32 + 8 pad)
#define BPAD    40
#define NTHR    512

// smem layout (bytes)
#define A_BYTES (TM*APAD*2)            // 10240
#define B_BYTES (CH*BPAD*2)            // 30720
#define SM_PARAM_OFF (2*A_BYTES + 2*B_BYTES)         // 81920
#define SM_PART_OFF  (SM_PARAM_OFF + 4*CH*4)         // + bias,gamma,beta,wl
#define SM_MEAN_OFF  (SM_PART_OFF + TM*8*4)
#define SM_RSTD_OFF  (SM_MEAN_OFF + TM*4)
#define SMEM_TOTAL   (SM_RSTD_OFF + TM*4)            // 93184

// ---------------- device scratch (no allocations allowed) ----------------
__device__ __nv_bfloat16 g_xbf[ROWS*CH];     // bf16 copy of x
__device__ __nv_bfloat16 g_h1 [ROWS*CH];     // layer-1 output (bf16)
__device__ __nv_bfloat16 g_w1T[CH*KTOT];     // w1 transposed: [o][k*CH+c]
__device__ __nv_bfloat16 g_w2T[CH*KTOT];
__device__ int           g_cum[ROWS];        // per-batch cumsum of durations

// ---------------- small prep kernels ----------------
__global__ void cvt_x_kernel(const float* __restrict__ x, int n2) {
    int i = blockIdx.x * blockDim.x + threadIdx.x;
    if (i < n2) {
        float2 v = reinterpret_cast<const float2*>(x)[i];
        reinterpret_cast<__nv_bfloat162*>(g_xbf)[i] = __floats2bfloat162_rn(v.x, v.y);
    }
}

// w [K, C, O] fp32 -> wT[o][k*C + c] bf16
__global__ void cvt_w_kernel(const float* __restrict__ w, int which) {
    int i = blockIdx.x * blockDim.x + threadIdx.x;
    if (i < CH * KTOT) {
        int o  = i / KTOT;
        int kc = i % KTOT;
        __nv_bfloat16 v = __float2bfloat16(w[(long)kc * CH + o]);
        if (which == 0) g_w1T[i] = v; else g_w2T[i] = v;
    }
}

__global__ void cumsum_kernel(const int* __restrict__ dur) {
    __shared__ int s[SEQ];
    int b = blockIdx.x, t = threadIdx.x;
    s[t] = dur[b * SEQ + t];
    __syncthreads();
    #pragma unroll
    for (int off = 1; off < SEQ; off <<= 1) {
        int v = (t >= off) ? s[t - off] : 0;
        __syncthreads();
        s[t] += v;
        __syncthreads();
    }
    g_cum[b * SEQ + t] = s[t];
}

// ---------------- mma helpers ----------------
__device__ __forceinline__ void mma16816(float* c, const uint32_t* a, uint32_t b0, uint32_t b1) {
    asm volatile(
        "mma.sync.aligned.m16n8k16.row.col.f32.bf16.bf16.f32 "
        "{%0,%1,%2,%3}, {%4,%5,%6,%7}, {%8,%9}, {%0,%1,%2,%3};\n"
        : "+f"(c[0]), "+f"(c[1]), "+f"(c[2]), "+f"(c[3])
        : "r"(a[0]), "r"(a[1]), "r"(a[2]), "r"(a[3]), "r"(b0), "r"(b1));
}

__device__ __forceinline__ void cp_async16(void* smem_dst, const void* gptr, int sz) {
    uint32_t d = (uint32_t)__cvta_generic_to_shared(smem_dst);
    asm volatile("cp.async.ca.shared.global [%0], [%1], 16, %2;\n" :: "r"(d), "l"(gptr), "r"(sz));
}
__device__ __forceinline__ void cp_async16(void* smem_dst, const void* gptr) {
    uint32_t d = (uint32_t)__cvta_generic_to_shared(smem_dst);
    asm volatile("cp.async.ca.shared.global [%0], [%1], 16;\n" :: "r"(d), "l"(gptr));
}
__device__ __forceinline__ void cp_commit() { asm volatile("cp.async.commit_group;\n"); }
__device__ __forceinline__ void cp_wait1()  { asm volatile("cp.async.wait_group 1;\n"); }
__device__ __forceinline__ void cp_wait0()  { asm volatile("cp.async.wait_group 0;\n"); }

// ---------------- fused conv(+bias) -> LayerNorm -> ReLU [-> store bf16 | -> @wl+bl -> exp] ----
// GEMM: M=32768 (rows), N=384, K=1152, conv SAME padding handled in A-tile loads.
template<bool PRED>
__global__ __launch_bounds__(NTHR, 1)
void conv_ln_kernel(const float* __restrict__ bias,
                    const float* __restrict__ gamma,
                    const float* __restrict__ beta,
                    const float* __restrict__ wl,
                    const float* __restrict__ bl,
                    float* __restrict__ pred)
{
    extern __shared__ char smem[];
    __nv_bfloat16* As    = (__nv_bfloat16*)smem;                    // [2][TM][APAD]
    __nv_bfloat16* Bs    = (__nv_bfloat16*)(smem + 2*A_BYTES);      // [2][CH][BPAD]
    float* sBias  = (float*)(smem + SM_PARAM_OFF);
    float* sGamma = sBias  + CH;
    float* sBeta  = sGamma + CH;
    float* sWl    = sBeta  + CH;
    float* sPart  = (float*)(smem + SM_PART_OFF);   // [TM][8]
    float* sMean  = (float*)(smem + SM_MEAN_OFF);   // [TM]
    float* sRstd  = (float*)(smem + SM_RSTD_OFF);   // [TM]

    const __nv_bfloat16* Ain = PRED ? g_h1  : g_xbf;
    const __nv_bfloat16* WT  = PRED ? g_w2T : g_w1T;

    int tid  = threadIdx.x;
    int bidx = blockIdx.x;            // 0..255
    int b    = bidx >> 3;             // 8 tiles per batch (1024/128)
    int s0   = (bidx & 7) * TM;
    long rowBase = (long)b * SEQ;

    if (tid < CH) {
        sBias[tid]  = bias[tid];
        sGamma[tid] = gamma[tid];
        sBeta[tid]  = beta[tid];
        sWl[tid]    = PRED ? wl[tid] : 0.0f;
    }

    // ---- tile loader (cp.async) ----
    auto load_tile = [&](int ci, int buf) {
        int k  = ci / 12;             // conv tap 0..2
        int c0 = (ci % 12) * KC;      // channel base within tap
        __nv_bfloat16* Ad = As + buf * (TM * APAD);
        __nv_bfloat16* Bd = Bs + buf * (CH * BPAD);
        {   // A: 128 rows x 64B = 512 x 16B reqs, 1 per thread
            int r = tid >> 2, seg = tid & 3;
            int gs = s0 + r + k - 1;                // batch-local padded row
            bool ok = (unsigned)gs < (unsigned)SEQ;
            const __nv_bfloat16* src = ok ? (Ain + (rowBase + gs) * CH + c0 + seg * 8) : Ain;
            cp_async16(Ad + r * APAD + seg * 8, src, ok ? 16 : 0);
        }
        // B: 384 rows x 64B = 1536 reqs, 3 per thread
        #pragma unroll
        for (int e = 0; e < 3; e++) {
            int j = tid + e * NTHR;
            int n = j >> 2, seg = j & 3;
            cp_async16(Bd + n * BPAD + seg * 8, WT + (long)n * KTOT + ci * KC + seg * 8);
        }
    };

    int wid = tid >> 5, lane = tid & 31;
    int wm = wid >> 2, wn = wid & 3;   // 4x4 warp grid; warp tile 32(M) x 96(N)
    int g = lane >> 2, tg = lane & 3;

    float c[2][12][4];
    #pragma unroll
    for (int mt = 0; mt < 2; mt++)
        #pragma unroll
        for (int nt = 0; nt < 12; nt++)
            #pragma unroll
            for (int i = 0; i < 4; i++) c[mt][nt][i] = 0.0f;

    load_tile(0, 0); cp_commit();
    load_tile(1, 1); cp_commit();

    for (int ci = 0; ci < NITER; ci++) {
        int buf = ci & 1;
        if (ci < NITER - 1) cp_wait1(); else cp_wait0();
        __syncthreads();

        const __nv_bfloat16* Ab = As + buf * (TM * APAD);
        const __nv_bfloat16* Bb = Bs + buf * (CH * BPAD);
        #pragma unroll
        for (int ks = 0; ks < 2; ks++) {
            uint32_t a[2][4];
            #pragma unroll
            for (int mt = 0; mt < 2; mt++) {
                int row = wm * 32 + mt * 16 + g;
                int col = ks * 16 + tg * 2;
                a[mt][0] = *(const uint32_t*)(Ab + row * APAD + col);
                a[mt][1] = *(const uint32_t*)(Ab + (row + 8) * APAD + col);
                a[mt][2] = *(const uint32_t*)(Ab + row * APAD + col + 8);
                a[mt][3] = *(const uint32_t*)(Ab + (row + 8) * APAD + col + 8);
            }
            #pragma unroll
            for (int nt = 0; nt < 12; nt++) {
                int n = wn * 96 + nt * 8 + g;
                uint32_t b0 = *(const uint32_t*)(Bb + n * BPAD + ks * 16 + tg * 2);
                uint32_t b1 = *(const uint32_t*)(Bb + n * BPAD + ks * 16 + tg * 2 + 8);
                mma16816(c[0][nt], a[0], b0, b1);
                mma16816(c[1][nt], a[1], b0, b1);
            }
        }
        __syncthreads();
        if (ci + 2 < NITER) { load_tile(ci + 2, buf); cp_commit(); }
    }

    // ---- epilogue: +bias, LayerNorm stats ----
    float psum[2][2] = {{0,0},{0,0}}, psq[2][2] = {{0,0},{0,0}};
    #pragma unroll
    for (int mt = 0; mt < 2; mt++)
        #pragma unroll
        for (int nt = 0; nt < 12; nt++) {
            int col0 = wn * 96 + nt * 8 + tg * 2;
            float bb0 = sBias[col0], bb1 = sBias[col0 + 1];
            c[mt][nt][0] += bb0; c[mt][nt][1] += bb1;
            c[mt][nt][2] += bb0; c[mt][nt][3] += bb1;
            psum[mt][0] += c[mt][nt][0] + c[mt][nt][1];
            psq [mt][0] += c[mt][nt][0]*c[mt][nt][0] + c[mt][nt][1]*c[mt][nt][1];
            psum[mt][1] += c[mt][nt][2] + c[mt][nt][3];
            psq [mt][1] += c[mt][nt][2]*c[mt][nt][2] + c[mt][nt][3]*c[mt][nt][3];
        }
    #pragma unroll
    for (int mt = 0; mt < 2; mt++)
        #pragma unroll
        for (int hi = 0; hi < 2; hi++) {
            float s = psum[mt][hi], q = psq[mt][hi];
            s += __shfl_xor_sync(0xffffffffu, s, 1); s += __shfl_xor_sync(0xffffffffu, s, 2);
            q += __shfl_xor_sync(0xffffffffu, q, 1); q += __shfl_xor_sync(0xffffffffu, q, 2);
            if (tg == 0) {
                int r = wm * 32 + mt * 16 + g + 8 * hi;
                sPart[r * 8 + wn] = s;
                sPart[r * 8 + 4 + wn] = q;
            }
        }
    __syncthreads();
    if (tid < TM) {
        float s = sPart[tid*8+0] + sPart[tid*8+1] + sPart[tid*8+2] + sPart[tid*8+3];
        float q = sPart[tid*8+4] + sPart[tid*8+5] + sPart[tid*8+6] + sPart[tid*8+7];
        float mean = s * (1.0f / CH);
        float var  = q * (1.0f / CH) - mean * mean;
        sMean[tid] = mean;
        sRstd[tid] = rsqrtf(var + 1e-5f);
    }
    __syncthreads();

    // ---- normalize + relu; store bf16 OR fused linear+exp ----
    float pd[2][2] = {{0,0},{0,0}};
    #pragma unroll
    for (int mt = 0; mt < 2; mt++) {
        int r0 = wm * 32 + mt * 16 + g;
        float m0 = sMean[r0],   rs0 = sRstd[r0];
        float m1 = sMean[r0+8], rs1 = sRstd[r0+8];
        #pragma unroll
        for (int nt = 0; nt < 12; nt++) {
            int col0 = wn * 96 + nt * 8 + tg * 2;
            float ga0 = sGamma[col0], ga1 = sGamma[col0+1];
            float be0 = sBeta[col0],  be1 = sBeta[col0+1];
            float v0 = fmaxf(0.f, (c[mt][nt][0] - m0) * rs0 * ga0 + be0);
            float v1 = fmaxf(0.f, (c[mt][nt][1] - m0) * rs0 * ga1 + be1);
            float v2 = fmaxf(0.f, (c[mt][nt][2] - m1) * rs1 * ga0 + be0);
            float v3 = fmaxf(0.f, (c[mt][nt][3] - m1) * rs1 * ga1 + be1);
            if (!PRED) {
                long base0 = (rowBase + s0 + r0) * CH + col0;
                *(__nv_bfloat162*)(g_h1 + base0)            = __floats2bfloat162_rn(v0, v1);
                *(__nv_bfloat162*)(g_h1 + base0 + 8 * CH)   = __floats2bfloat162_rn(v2, v3);
            } else {
                float w0 = sWl[col0], w1v = sWl[col0 + 1];
                pd[mt][0] += v0 * w0 + v1 * w1v;
                pd[mt][1] += v2 * w0 + v3 * w1v;
            }
        }
    }
    if (PRED) {
        #pragma unroll
        for (int mt = 0; mt < 2; mt++)
            #pragma unroll
            for (int hi = 0; hi < 2; hi++) {
                float s = pd[mt][hi];
                s += __shfl_xor_sync(0xffffffffu, s, 1);
                s += __shfl_xor_sync(0xffffffffu, s, 2);
                if (tg == 0) {
                    int r = wm * 32 + mt * 16 + g + 8 * hi;
                    sPart[r * 8 + wn] = s;
                }
            }
        __syncthreads();
        if (tid < TM) {
            float s = sPart[tid*8+0] + sPart[tid*8+1] + sPart[tid*8+2] + sPart[tid*8+3];
            pred[rowBase + s0 + tid] = expf(s + bl[0]);
        }
    }
}

// ---------------- length regulation (exact gather of fp32 x) ----------------
// warp per output row t; binary search over smem cumsum
__global__ void gather_kernel(const float* __restrict__ x, float* __restrict__ out) {
    __shared__ int sc[SEQ];
    int b = blockIdx.y;
    for (int i = threadIdx.x; i < SEQ; i += blockDim.x) sc[i] = g_cum[b * SEQ + i];
    __syncthreads();

    int warp = threadIdx.x >> 5, lane = threadIdx.x & 31;
    int t = blockIdx.x * 8 + warp;            // 0..3071
    int total = sc[SEQ - 1];
    bool valid = t < total;
    int lo = 0, hi = SEQ;
    while (lo < hi) { int mid = (lo + hi) >> 1; if (sc[mid] <= t) lo = mid + 1; else hi = mid; }
    int src = min(lo, SEQ - 1);

    const float4* xp = (const float4*)(x + ((long)b * SEQ + src) * CH);
    float4* op = (float4*)(out + ((long)b * MAXOUT + t) * CH);
    #pragma unroll
    for (int i = 0; i < 3; i++) {
        float4 v = valid ? xp[lane + 32 * i] : make_float4(0.f, 0.f, 0.f, 0.f);
        op[lane + 32 * i] = v;
    }
}

// ---------------- launch ----------------
extern "C" void kernel_launch(void* const* d_in, const int* in_sizes, int n_in,
                              void* d_out, int out_size) {
    const float* x     = (const float*)d_in[0];
    const int*   dur   = (const int*)  d_in[1];
    const float* w1    = (const float*)d_in[2];
    const float* b1    = (const float*)d_in[3];
    const float* g1    = (const float*)d_in[4];
    const float* beta1 = (const float*)d_in[5];
    const float* w2    = (const float*)d_in[6];
    const float* b2    = (const float*)d_in[7];
    const float* g2    = (const float*)d_in[8];
    const float* beta2 = (const float*)d_in[9];
    const float* wl    = (const float*)d_in[10];
    const float* bl    = (const float*)d_in[11];

    float* res  = (float*)d_out;
    float* pred = res + (long)BATCH * MAXOUT * CH;

    cudaFuncSetAttribute(conv_ln_kernel<false>, cudaFuncAttributeMaxDynamicSharedMemorySize, SMEM_TOTAL);
    cudaFuncSetAttribute(conv_ln_kernel<true>,  cudaFuncAttributeMaxDynamicSharedMemorySize, SMEM_TOTAL);

    // prep: bf16 conversions + cumsum
    int n2 = ROWS * CH / 2;
    cvt_x_kernel<<<(n2 + 255) / 256, 256>>>(x, n2);
    cvt_w_kernel<<<(CH * KTOT + 255) / 256, 256>>>(w1, 0);
    cvt_w_kernel<<<(CH * KTOT + 255) / 256, 256>>>(w2, 1);
    cumsum_kernel<<<BATCH, SEQ>>>(dur);

    // layer 1: conv+bias+LN+relu -> g_h1 (bf16)
    conv_ln_kernel<false><<<ROWS / TM, NTHR, SMEM_TOTAL>>>(b1, g1, beta1, nullptr, nullptr, nullptr);
    // layer 2: conv+bias+LN+relu -> @wl + bl -> exp -> pred
    conv_ln_kernel<true><<<ROWS / TM, NTHR, SMEM_TOTAL>>>(b2, g2, beta2, wl, bl, pred);

    // length regulation (exact fp32 gather, zero-fills invalid tail)
    gather_kernel<<<dim3(MAXOUT / 8, BATCH), 256>>>(x, res);
}

// round 6
// speedup vs baseline: 1.0199x; 1.0199x over previous
#include <cuda_runtime.h>
#include <cuda_bf16.h>
#include <cstdint>
#include <math.h>

// ---------------- problem constants ----------------
#define BATCH   32
#define SEQ     1024
#define CH      384          // C == H == 384
#define KTOT    1152         // 3 * 384
#define MAXOUT  3072
#define ROWS    (BATCH*SEQ)  // 32768

// GEMM tiling
#define TM      128
#define KC      32
#define NITER   (KTOT/KC)    // 36
#define APAD    40           // halves per A smem row (32 + 8 pad) -> 80B stride, LDSM conflict-free
#define BPAD    40
#define NTHR    512
#define NSTAGE  3

// smem layout (bytes)
#define A_BYTES (TM*APAD*2)                    // 10240
#define B_BYTES (CH*BPAD*2)                    // 30720
#define OFF_B     (NSTAGE*A_BYTES)             // 30720
#define OFF_PARAM (OFF_B + NSTAGE*B_BYTES)     // 122880
#define OFF_PART  (OFF_PARAM + 4*CH*4)         // 129024
#define OFF_MEAN  (OFF_PART + TM*8*4)          // 133120
#define OFF_RSTD  (OFF_MEAN + TM*4)            // 133632
#define SMEM_TOTAL (OFF_RSTD + TM*4)           // 134144

// ---------------- device scratch (no allocations allowed) ----------------
__device__ __nv_bfloat16 g_xbf[ROWS*CH];     // bf16 copy of x
__device__ __nv_bfloat16 g_h1 [ROWS*CH];     // layer-1 output (bf16)
__device__ __nv_bfloat16 g_w1T[CH*KTOT];     // w1 transposed: [o][k*CH+c]
__device__ __nv_bfloat16 g_w2T[CH*KTOT];
__device__ int           g_cum[ROWS];        // per-batch cumsum of durations

// ---------------- small prep kernels ----------------
__global__ void cvt_x_kernel(const float* __restrict__ x, int n2) {
    int i = blockIdx.x * blockDim.x + threadIdx.x;
    if (i < n2) {
        float2 v = reinterpret_cast<const float2*>(x)[i];
        reinterpret_cast<__nv_bfloat162*>(g_xbf)[i] = __floats2bfloat162_rn(v.x, v.y);
    }
}

// w [K, C, O] fp32 -> wT[o][k*C + c] bf16
__global__ void cvt_w_kernel(const float* __restrict__ w, int which) {
    int i = blockIdx.x * blockDim.x + threadIdx.x;
    if (i < CH * KTOT) {
        int o  = i / KTOT;
        int kc = i % KTOT;
        __nv_bfloat16 v = __float2bfloat16(w[(size_t)kc * CH + o]);
        if (which == 0) g_w1T[i] = v; else g_w2T[i] = v;
    }
}

__global__ void cumsum_kernel(const int* __restrict__ dur) {
    __shared__ int s[SEQ];
    int b = blockIdx.x, t = threadIdx.x;
    s[t] = dur[b * SEQ + t];
    __syncthreads();
    #pragma unroll
    for (int off = 1; off < SEQ; off <<= 1) {
        int v = (t >= off) ? s[t - off] : 0;
        __syncthreads();
        s[t] += v;
        __syncthreads();
    }
    g_cum[b * SEQ + t] = s[t];
}

// ---------------- ptx helpers ----------------
__device__ __forceinline__ void mma16816(float* c, const uint32_t* a, uint32_t b0, uint32_t b1) {
    asm volatile(
        "mma.sync.aligned.m16n8k16.row.col.f32.bf16.bf16.f32 "
        "{%0,%1,%2,%3}, {%4,%5,%6,%7}, {%8,%9}, {%0,%1,%2,%3};\n"
        : "+f"(c[0]), "+f"(c[1]), "+f"(c[2]), "+f"(c[3])
        : "r"(a[0]), "r"(a[1]), "r"(a[2]), "r"(a[3]), "r"(b0), "r"(b1));
}
__device__ __forceinline__ void ldsm4(uint32_t* r, uint32_t addr) {
    asm volatile("ldmatrix.sync.aligned.m8n8.x4.shared.b16 {%0,%1,%2,%3}, [%4];\n"
                 : "=r"(r[0]), "=r"(r[1]), "=r"(r[2]), "=r"(r[3]) : "r"(addr));
}
__device__ __forceinline__ void cp_async16(uint32_t dst, const void* gptr, int sz) {
    asm volatile("cp.async.cg.shared.global [%0], [%1], 16, %2;\n" :: "r"(dst), "l"(gptr), "r"(sz));
}
__device__ __forceinline__ void cp_async16(uint32_t dst, const void* gptr) {
    asm volatile("cp.async.cg.shared.global [%0], [%1], 16;\n" :: "r"(dst), "l"(gptr));
}
__device__ __forceinline__ void cp_commit() { asm volatile("cp.async.commit_group;\n"); }
__device__ __forceinline__ void cp_wait1()  { asm volatile("cp.async.wait_group 1;\n"); }
__device__ __forceinline__ void cp_wait0()  { asm volatile("cp.async.wait_group 0;\n"); }

// ---------------- fused conv(+bias) -> LayerNorm -> ReLU [-> store bf16 | -> @wl+bl -> exp] ----
// GEMM: M=32768 (rows), N=384, K=1152, conv SAME padding handled in A-tile loads.
template<bool PRED>
__global__ __launch_bounds__(NTHR, 1)
void conv_ln_kernel(const float* __restrict__ bias,
                    const float* __restrict__ gamma,
                    const float* __restrict__ beta,
                    const float* __restrict__ wl,
                    const float* __restrict__ bl,
                    float* __restrict__ pred)
{
    extern __shared__ char smem[];
    const uint32_t smem_base = (uint32_t)__cvta_generic_to_shared(smem);
    float* sBias  = (float*)(smem + OFF_PARAM);
    float* sGamma = sBias  + CH;
    float* sBeta  = sGamma + CH;
    float* sWl    = sBeta  + CH;
    float* sPart  = (float*)(smem + OFF_PART);   // [TM][8]
    float* sMean  = (float*)(smem + OFF_MEAN);   // [TM]
    float* sRstd  = (float*)(smem + OFF_RSTD);   // [TM]

    const __nv_bfloat16* Ain = PRED ? g_h1  : g_xbf;
    const __nv_bfloat16* WT  = PRED ? g_w2T : g_w1T;

    const int tid  = threadIdx.x;
    const int bidx = blockIdx.x;            // 0..255
    const int b    = bidx >> 3;             // 8 tiles per batch (1024/128)
    const int s0   = (bidx & 7) * TM;
    const size_t rowBase = (size_t)b * SEQ;

    if (tid < CH) {
        sBias[tid]  = bias[tid];
        sGamma[tid] = gamma[tid];
        sBeta[tid]  = beta[tid];
        sWl[tid]    = PRED ? wl[tid] : 0.0f;
    }

    // ---- tile loader (cp.async, SW-free padded layout) ----
    auto load_tile = [&](int ci, int st) {
        const int k  = ci / 12;             // conv tap 0..2
        const int c0 = (ci % 12) * KC;      // channel base within tap
        const uint32_t Ad = smem_base + st * A_BYTES;
        const uint32_t Bd = smem_base + OFF_B + st * B_BYTES;
        {   // A: 128 rows x 64B = 512 x 16B reqs, 1 per thread
            int r = tid >> 2, seg = tid & 3;
            int gs = s0 + r + k - 1;                // batch-local padded row
            bool ok = (unsigned)gs < (unsigned)SEQ;
            const void* src = ok ? (const void*)(Ain + (rowBase + gs) * CH + c0 + seg * 8)
                                 : (const void*)Ain;
            cp_async16(Ad + (r * APAD + seg * 8) * 2, src, ok ? 16 : 0);
        }
        // B: 384 rows x 64B = 1536 reqs, 3 per thread
        #pragma unroll
        for (int e = 0; e < 3; e++) {
            int j = tid + e * NTHR;
            int n = j >> 2, seg = j & 3;
            cp_async16(Bd + (n * BPAD + seg * 8) * 2,
                       WT + (size_t)n * KTOT + ci * KC + seg * 8);
        }
    };

    const int wid = tid >> 5, lane = tid & 31;
    const int wm = wid >> 2, wn = wid & 3;   // 4x4 warp grid; warp tile 32(M) x 96(N)

    // ldmatrix lane-address components
    // A x4: m0 rows lo / k lo, m1 rows hi / k lo, m2 rows lo / k hi, m3 rows hi / k hi
    const int aRow = wm * 32 + (lane & 7) + ((lane >> 3) & 1) * 8;
    const int aCol = (lane >> 4) * 8;                    // halves
    const uint32_t aBase = (uint32_t)((aRow * APAD + aCol) * 2);
    // B x4: m0 n-lo/k-lo, m1 n-lo/k-hi, m2 n-hi/k-lo, m3 n-hi/k-hi
    const int bRow = wn * 96 + (lane & 7) + ((lane >> 4) & 1) * 8;
    const int bCol = ((lane >> 3) & 1) * 8;              // halves
    const uint32_t bBase = (uint32_t)((bRow * BPAD + bCol) * 2);

    float c[2][12][4];
    #pragma unroll
    for (int mt = 0; mt < 2; mt++)
        #pragma unroll
        for (int nt = 0; nt < 12; nt++)
            #pragma unroll
            for (int i = 0; i < 4; i++) c[mt][nt][i] = 0.0f;

    load_tile(0, 0); cp_commit();
    load_tile(1, 1); cp_commit();

    for (int ci = 0; ci < NITER; ci++) {
        const int st = ci % NSTAGE;
        if (ci < NITER - 1) cp_wait1(); else cp_wait0();
        __syncthreads();
        if (ci + 2 < NITER) { load_tile(ci + 2, (ci + 2) % NSTAGE); cp_commit(); }

        const uint32_t Asb = smem_base + st * A_BYTES + aBase;
        const uint32_t Bsb = smem_base + OFF_B + st * B_BYTES + bBase;
        #pragma unroll
        for (int ks = 0; ks < 2; ks++) {
            uint32_t a[2][4];
            ldsm4(a[0], Asb + ks * 32);                       // rows wm*32 +  0..15
            ldsm4(a[1], Asb + 16 * APAD * 2 + ks * 32);       // rows wm*32 + 16..31
            #pragma unroll
            for (int np = 0; np < 6; np++) {
                uint32_t bb[4];                               // 2 n8 fragments
                ldsm4(bb, Bsb + np * 16 * BPAD * 2 + ks * 32);
                mma16816(c[0][2*np  ], a[0], bb[0], bb[1]);
                mma16816(c[1][2*np  ], a[1], bb[0], bb[1]);
                mma16816(c[0][2*np+1], a[0], bb[2], bb[3]);
                mma16816(c[1][2*np+1], a[1], bb[2], bb[3]);
            }
        }
    }
    __syncthreads();

    // ---- epilogue: +bias, LayerNorm stats ----
    const int g = lane >> 2, tg = lane & 3;
    float psum[2][2] = {{0,0},{0,0}}, psq[2][2] = {{0,0},{0,0}};
    #pragma unroll
    for (int mt = 0; mt < 2; mt++)
        #pragma unroll
        for (int nt = 0; nt < 12; nt++) {
            int col0 = wn * 96 + nt * 8 + tg * 2;
            float bb0 = sBias[col0], bb1 = sBias[col0 + 1];
            c[mt][nt][0] += bb0; c[mt][nt][1] += bb1;
            c[mt][nt][2] += bb0; c[mt][nt][3] += bb1;
            psum[mt][0] += c[mt][nt][0] + c[mt][nt][1];
            psq [mt][0] += c[mt][nt][0]*c[mt][nt][0] + c[mt][nt][1]*c[mt][nt][1];
            psum[mt][1] += c[mt][nt][2] + c[mt][nt][3];
            psq [mt][1] += c[mt][nt][2]*c[mt][nt][2] + c[mt][nt][3]*c[mt][nt][3];
        }
    #pragma unroll
    for (int mt = 0; mt < 2; mt++)
        #pragma unroll
        for (int hi = 0; hi < 2; hi++) {
            float s = psum[mt][hi], q = psq[mt][hi];
            s += __shfl_xor_sync(0xffffffffu, s, 1); s += __shfl_xor_sync(0xffffffffu, s, 2);
            q += __shfl_xor_sync(0xffffffffu, q, 1); q += __shfl_xor_sync(0xffffffffu, q, 2);
            if (tg == 0) {
                int r = wm * 32 + mt * 16 + g + 8 * hi;
                sPart[r * 8 + wn] = s;
                sPart[r * 8 + 4 + wn] = q;
            }
        }
    __syncthreads();
    if (tid < TM) {
        float s = sPart[tid*8+0] + sPart[tid*8+1] + sPart[tid*8+2] + sPart[tid*8+3];
        float q = sPart[tid*8+4] + sPart[tid*8+5] + sPart[tid*8+6] + sPart[tid*8+7];
        float mean = s * (1.0f / CH);
        float var  = q * (1.0f / CH) - mean * mean;
        sMean[tid] = mean;
        sRstd[tid] = rsqrtf(var + 1e-5f);
    }
    __syncthreads();

    // ---- normalize + relu; store bf16 OR fused linear+exp ----
    float pd[2][2] = {{0,0},{0,0}};
    #pragma unroll
    for (int mt = 0; mt < 2; mt++) {
        int r0 = wm * 32 + mt * 16 + g;
        float m0 = sMean[r0],   rs0 = sRstd[r0];
        float m1 = sMean[r0+8], rs1 = sRstd[r0+8];
        #pragma unroll
        for (int nt = 0; nt < 12; nt++) {
            int col0 = wn * 96 + nt * 8 + tg * 2;
            float ga0 = sGamma[col0], ga1 = sGamma[col0+1];
            float be0 = sBeta[col0],  be1 = sBeta[col0+1];
            float v0 = fmaxf(0.f, (c[mt][nt][0] - m0) * rs0 * ga0 + be0);
            float v1 = fmaxf(0.f, (c[mt][nt][1] - m0) * rs0 * ga1 + be1);
            float v2 = fmaxf(0.f, (c[mt][nt][2] - m1) * rs1 * ga0 + be0);
            float v3 = fmaxf(0.f, (c[mt][nt][3] - m1) * rs1 * ga1 + be1);
            if (!PRED) {
                size_t base0 = (rowBase + s0 + r0) * CH + col0;
                *(__nv_bfloat162*)(g_h1 + base0)          = __floats2bfloat162_rn(v0, v1);
                *(__nv_bfloat162*)(g_h1 + base0 + 8 * CH) = __floats2bfloat162_rn(v2, v3);
            } else {
                float w0 = sWl[col0], w1v = sWl[col0 + 1];
                pd[mt][0] += v0 * w0 + v1 * w1v;
                pd[mt][1] += v2 * w0 + v3 * w1v;
            }
        }
    }
    if (PRED) {
        #pragma unroll
        for (int mt = 0; mt < 2; mt++)
            #pragma unroll
            for (int hi = 0; hi < 2; hi++) {
                float s = pd[mt][hi];
                s += __shfl_xor_sync(0xffffffffu, s, 1);
                s += __shfl_xor_sync(0xffffffffu, s, 2);
                if (tg == 0) {
                    int r = wm * 32 + mt * 16 + g + 8 * hi;
                    sPart[r * 8 + wn] = s;
                }
            }
        __syncthreads();
        if (tid < TM) {
            float s = sPart[tid*8+0] + sPart[tid*8+1] + sPart[tid*8+2] + sPart[tid*8+3];
            pred[rowBase + s0 + tid] = expf(s + bl[0]);
        }
    }
}

// ---------------- length regulation (exact gather of fp32 x) ----------------
// warp per output row t; binary search over smem cumsum
__global__ void gather_kernel(const float* __restrict__ x, float* __restrict__ out) {
    __shared__ int sc[SEQ];
    int b = blockIdx.y;
    for (int i = threadIdx.x; i < SEQ; i += blockDim.x) sc[i] = g_cum[b * SEQ + i];
    __syncthreads();

    int warp = threadIdx.x >> 5, lane = threadIdx.x & 31;
    int t = blockIdx.x * 8 + warp;            // 0..3071
    int total = sc[SEQ - 1];
    bool valid = t < total;
    int lo = 0, hi = SEQ;
    while (lo < hi) { int mid = (lo + hi) >> 1; if (sc[mid] <= t) lo = mid + 1; else hi = mid; }
    int src = min(lo, SEQ - 1);

    const float4* xp = (const float4*)(x + ((size_t)b * SEQ + src) * CH);
    float4* op = (float4*)(out + ((size_t)b * MAXOUT + t) * CH);
    #pragma unroll
    for (int i = 0; i < 3; i++) {
        float4 v = valid ? xp[lane + 32 * i] : make_float4(0.f, 0.f, 0.f, 0.f);
        op[lane + 32 * i] = v;
    }
}

// ---------------- launch ----------------
extern "C" void kernel_launch(void* const* d_in, const int* in_sizes, int n_in,
                              void* d_out, int out_size) {
    const float* x     = (const float*)d_in[0];
    const int*   dur   = (const int*)  d_in[1];
    const float* w1    = (const float*)d_in[2];
    const float* b1    = (const float*)d_in[3];
    const float* g1    = (const float*)d_in[4];
    const float* beta1 = (const float*)d_in[5];
    const float* w2    = (const float*)d_in[6];
    const float* b2    = (const float*)d_in[7];
    const float* g2    = (const float*)d_in[8];
    const float* beta2 = (const float*)d_in[9];
    const float* wl    = (const float*)d_in[10];
    const float* bl    = (const float*)d_in[11];

    float* res  = (float*)d_out;
    float* pred = res + (size_t)BATCH * MAXOUT * CH;

    cudaFuncSetAttribute(conv_ln_kernel<false>, cudaFuncAttributeMaxDynamicSharedMemorySize, SMEM_TOTAL);
    cudaFuncSetAttribute(conv_ln_kernel<true>,  cudaFuncAttributeMaxDynamicSharedMemorySize, SMEM_TOTAL);

    // prep: bf16 conversions + cumsum
    int n2 = ROWS * CH / 2;
    cvt_x_kernel<<<(n2 + 255) / 256, 256>>>(x, n2);
    cvt_w_kernel<<<(CH * KTOT + 255) / 256, 256>>>(w1, 0);
    cvt_w_kernel<<<(CH * KTOT + 255) / 256, 256>>>(w2, 1);
    cumsum_kernel<<<BATCH, SEQ>>>(dur);

    // layer 1: conv+bias+LN+relu -> g_h1 (bf16)
    conv_ln_kernel<false><<<ROWS / TM, NTHR, SMEM_TOTAL>>>(b1, g1, beta1, nullptr, nullptr, nullptr);
    // layer 2: conv+bias+LN+relu -> @wl + bl -> exp -> pred
    conv_ln_kernel<true><<<ROWS / TM, NTHR, SMEM_TOTAL>>>(b2, g2, beta2, wl, bl, pred);

    // length regulation (exact fp32 gather, zero-fills invalid tail)
    gather_kernel<<<dim3(MAXOUT / 8, BATCH), 256>>>(x, res);
}

// round 7
// speedup vs baseline: 1.1146x; 1.0928x over previous
#include <cuda_runtime.h>
#include <cuda_bf16.h>
#include <cstdint>
#include <math.h>

// ---------------- problem constants ----------------
#define BATCH   32
#define SEQ     1024
#define CH      384          // C == H == 384
#define KTOT    1152         // 3 * 384
#define MAXOUT  3072
#define ROWS    (BATCH*SEQ)  // 32768

// GEMM tiling
#define TM      128
#define KC      32
#define NITER   (KTOT/KC)    // 36
#define APAD    40           // halves per A smem row (32 + 8 pad) -> 80B stride, LDSM conflict-free
#define BPAD    40
#define NTHR    512
#define NSTAGE  4

// smem layout (bytes)
#define A_BYTES (TM*APAD*2)                    // 10240
#define B_BYTES (CH*BPAD*2)                    // 30720
#define OFF_B     (NSTAGE*A_BYTES)             // 40960
#define OFF_PARAM (OFF_B + NSTAGE*B_BYTES)     // 163840
#define OFF_PART  (OFF_PARAM + 4*CH*4)         // 169984
#define OFF_MEAN  (OFF_PART + TM*8*4)          // 174080
#define OFF_RSTD  (OFF_MEAN + TM*4)            // 174592
#define SMEM_TOTAL (OFF_RSTD + TM*4)           // 175104

// ---------------- device scratch (no allocations allowed) ----------------
__device__ __nv_bfloat16 g_xbf[ROWS*CH];     // bf16 copy of x
__device__ __nv_bfloat16 g_h1 [ROWS*CH];     // layer-1 output (bf16)
__device__ __nv_bfloat16 g_w1T[CH*KTOT];     // w1 transposed: [o][k*CH+c]
__device__ __nv_bfloat16 g_w2T[CH*KTOT];
__device__ int           g_cum[ROWS];        // per-batch cumsum of durations

// ---------------- small prep kernels ----------------
__global__ void cvt_x_kernel(const float* __restrict__ x, int n2) {
    int i = blockIdx.x * blockDim.x + threadIdx.x;
    if (i < n2) {
        float2 v = reinterpret_cast<const float2*>(x)[i];
        reinterpret_cast<__nv_bfloat162*>(g_xbf)[i] = __floats2bfloat162_rn(v.x, v.y);
    }
}

// w [K, C, O] fp32 -> wT[o][k*C + c] bf16
__global__ void cvt_w_kernel(const float* __restrict__ w, int which) {
    int i = blockIdx.x * blockDim.x + threadIdx.x;
    if (i < CH * KTOT) {
        int o  = i / KTOT;
        int kc = i % KTOT;
        __nv_bfloat16 v = __float2bfloat16(w[(size_t)kc * CH + o]);
        if (which == 0) g_w1T[i] = v; else g_w2T[i] = v;
    }
}

__global__ void cumsum_kernel(const int* __restrict__ dur) {
    __shared__ int s[SEQ];
    int b = blockIdx.x, t = threadIdx.x;
    s[t] = dur[b * SEQ + t];
    __syncthreads();
    #pragma unroll
    for (int off = 1; off < SEQ; off <<= 1) {
        int v = (t >= off) ? s[t - off] : 0;
        __syncthreads();
        s[t] += v;
        __syncthreads();
    }
    g_cum[b * SEQ + t] = s[t];
}

// ---------------- ptx helpers ----------------
__device__ __forceinline__ void mma16816(float* c, const uint32_t* a, uint32_t b0, uint32_t b1) {
    asm volatile(
        "mma.sync.aligned.m16n8k16.row.col.f32.bf16.bf16.f32 "
        "{%0,%1,%2,%3}, {%4,%5,%6,%7}, {%8,%9}, {%0,%1,%2,%3};\n"
        : "+f"(c[0]), "+f"(c[1]), "+f"(c[2]), "+f"(c[3])
        : "r"(a[0]), "r"(a[1]), "r"(a[2]), "r"(a[3]), "r"(b0), "r"(b1));
}
__device__ __forceinline__ void ldsm4(uint32_t* r, uint32_t addr) {
    asm volatile("ldmatrix.sync.aligned.m8n8.x4.shared.b16 {%0,%1,%2,%3}, [%4];\n"
                 : "=r"(r[0]), "=r"(r[1]), "=r"(r[2]), "=r"(r[3]) : "r"(addr));
}
__device__ __forceinline__ void cp_async16(uint32_t dst, const void* gptr, int sz) {
    asm volatile("cp.async.cg.shared.global [%0], [%1], 16, %2;\n" :: "r"(dst), "l"(gptr), "r"(sz));
}
__device__ __forceinline__ void cp_async16(uint32_t dst, const void* gptr) {
    asm volatile("cp.async.cg.shared.global [%0], [%1], 16;\n" :: "r"(dst), "l"(gptr));
}
__device__ __forceinline__ void cp_commit() { asm volatile("cp.async.commit_group;\n"); }
__device__ __forceinline__ void cp_wait2()  { asm volatile("cp.async.wait_group 2;\n"); }
__device__ __forceinline__ void cp_wait1()  { asm volatile("cp.async.wait_group 1;\n"); }
__device__ __forceinline__ void cp_wait0()  { asm volatile("cp.async.wait_group 0;\n"); }

// ---------------- fused conv(+bias) -> LayerNorm -> ReLU [-> store bf16 | -> @wl+bl -> exp] ----
// GEMM: M=32768 (rows), N=384, K=1152, conv SAME padding handled in A-tile loads.
template<bool PRED>
__global__ __launch_bounds__(NTHR, 1)
void conv_ln_kernel(const float* __restrict__ bias,
                    const float* __restrict__ gamma,
                    const float* __restrict__ beta,
                    const float* __restrict__ wl,
                    const float* __restrict__ bl,
                    float* __restrict__ pred)
{
    extern __shared__ char smem[];
    const uint32_t smem_base = (uint32_t)__cvta_generic_to_shared(smem);
    float* sBias  = (float*)(smem + OFF_PARAM);
    float* sGamma = sBias  + CH;
    float* sBeta  = sGamma + CH;
    float* sWl    = sBeta  + CH;
    float* sPart  = (float*)(smem + OFF_PART);   // [TM][8]
    float* sMean  = (float*)(smem + OFF_MEAN);   // [TM]
    float* sRstd  = (float*)(smem + OFF_RSTD);   // [TM]

    const __nv_bfloat16* Ain = PRED ? g_h1  : g_xbf;
    const __nv_bfloat16* WT  = PRED ? g_w2T : g_w1T;

    const int tid  = threadIdx.x;
    const int bidx = blockIdx.x;            // 0..255
    const int b    = bidx >> 3;             // 8 tiles per batch (1024/128)
    const int s0   = (bidx & 7) * TM;
    const size_t rowBase = (size_t)b * SEQ;

    if (tid < CH) {
        sBias[tid]  = bias[tid];
        sGamma[tid] = gamma[tid];
        sBeta[tid]  = beta[tid];
        sWl[tid]    = PRED ? wl[tid] : 0.0f;
    }

    // ---- tile loader (cp.async, padded layout) ----
    auto load_tile = [&](int ci, int st) {
        const int k  = ci / 12;             // conv tap 0..2
        const int c0 = (ci % 12) * KC;      // channel base within tap
        const uint32_t Ad = smem_base + st * A_BYTES;
        const uint32_t Bd = smem_base + OFF_B + st * B_BYTES;
        {   // A: 128 rows x 64B = 512 x 16B reqs, 1 per thread
            int r = tid >> 2, seg = tid & 3;
            int gs = s0 + r + k - 1;                // batch-local padded row
            bool ok = (unsigned)gs < (unsigned)SEQ;
            const void* src = ok ? (const void*)(Ain + (rowBase + gs) * CH + c0 + seg * 8)
                                 : (const void*)Ain;
            cp_async16(Ad + (r * APAD + seg * 8) * 2, src, ok ? 16 : 0);
        }
        // B: 384 rows x 64B = 1536 reqs, 3 per thread
        #pragma unroll
        for (int e = 0; e < 3; e++) {
            int j = tid + e * NTHR;
            int n = j >> 2, seg = j & 3;
            cp_async16(Bd + (n * BPAD + seg * 8) * 2,
                       WT + (size_t)n * KTOT + ci * KC + seg * 8);
        }
    };

    const int wid = tid >> 5, lane = tid & 31;
    const int wm = wid >> 2, wn = wid & 3;   // 4x4 warp grid; warp tile 32(M) x 96(N)

    // ldmatrix lane-address components
    const int aRow = wm * 32 + (lane & 7) + ((lane >> 3) & 1) * 8;
    const int aCol = (lane >> 4) * 8;                    // halves
    const uint32_t aBase = (uint32_t)((aRow * APAD + aCol) * 2);
    const int bRow = wn * 96 + (lane & 7) + ((lane >> 4) & 1) * 8;
    const int bCol = ((lane >> 3) & 1) * 8;              // halves
    const uint32_t bBase = (uint32_t)((bRow * BPAD + bCol) * 2);

    float c[2][12][4];
    #pragma unroll
    for (int mt = 0; mt < 2; mt++)
        #pragma unroll
        for (int nt = 0; nt < 12; nt++)
            #pragma unroll
            for (int i = 0; i < 4; i++) c[mt][nt][i] = 0.0f;

    load_tile(0, 0); cp_commit();
    load_tile(1, 1); cp_commit();

    for (int ci = 0; ci < NITER; ci++) {
        const int st = ci & 3;
        // prefetch BEFORE waiting: stage (ci+2)&3 was consumed in iter ci-2,
        // and every warp passed the barrier of iter ci-1 after finishing it.
        if (ci + 2 < NITER) { load_tile(ci + 2, (ci + 2) & 3); cp_commit(); cp_wait2(); }
        else if (ci == NITER - 2) cp_wait1();
        else cp_wait0();
        __syncthreads();

        const uint32_t Asb = smem_base + st * A_BYTES + aBase;
        const uint32_t Bsb = smem_base + OFF_B + st * B_BYTES + bBase;
        #pragma unroll
        for (int ks = 0; ks < 2; ks++) {
            uint32_t a[2][4];
            ldsm4(a[0], Asb + ks * 32);                       // rows wm*32 +  0..15
            ldsm4(a[1], Asb + 16 * APAD * 2 + ks * 32);       // rows wm*32 + 16..31
            #pragma unroll
            for (int np = 0; np < 6; np++) {
                uint32_t bb[4];                               // 2 n8 fragments
                ldsm4(bb, Bsb + np * 16 * BPAD * 2 + ks * 32);
                mma16816(c[0][2*np  ], a[0], bb[0], bb[1]);
                mma16816(c[1][2*np  ], a[1], bb[0], bb[1]);
                mma16816(c[0][2*np+1], a[0], bb[2], bb[3]);
                mma16816(c[1][2*np+1], a[1], bb[2], bb[3]);
            }
        }
    }
    __syncthreads();

    // ---- epilogue: +bias, LayerNorm stats ----
    const int g = lane >> 2, tg = lane & 3;
    float psum[2][2] = {{0,0},{0,0}}, psq[2][2] = {{0,0},{0,0}};
    #pragma unroll
    for (int mt = 0; mt < 2; mt++)
        #pragma unroll
        for (int nt = 0; nt < 12; nt++) {
            int col0 = wn * 96 + nt * 8 + tg * 2;
            float bb0 = sBias[col0], bb1 = sBias[col0 + 1];
            c[mt][nt][0] += bb0; c[mt][nt][1] += bb1;
            c[mt][nt][2] += bb0; c[mt][nt][3] += bb1;
            psum[mt][0] += c[mt][nt][0] + c[mt][nt][1];
            psq [mt][0] += c[mt][nt][0]*c[mt][nt][0] + c[mt][nt][1]*c[mt][nt][1];
            psum[mt][1] += c[mt][nt][2] + c[mt][nt][3];
            psq [mt][1] += c[mt][nt][2]*c[mt][nt][2] + c[mt][nt][3]*c[mt][nt][3];
        }
    #pragma unroll
    for (int mt = 0; mt < 2; mt++)
        #pragma unroll
        for (int hi = 0; hi < 2; hi++) {
            float s = psum[mt][hi], q = psq[mt][hi];
            s += __shfl_xor_sync(0xffffffffu, s, 1); s += __shfl_xor_sync(0xffffffffu, s, 2);
            q += __shfl_xor_sync(0xffffffffu, q, 1); q += __shfl_xor_sync(0xffffffffu, q, 2);
            if (tg == 0) {
                int r = wm * 32 + mt * 16 + g + 8 * hi;
                sPart[r * 8 + wn] = s;
                sPart[r * 8 + 4 + wn] = q;
            }
        }
    __syncthreads();
    if (tid < TM) {
        float s = sPart[tid*8+0] + sPart[tid*8+1] + sPart[tid*8+2] + sPart[tid*8+3];
        float q = sPart[tid*8+4] + sPart[tid*8+5] + sPart[tid*8+6] + sPart[tid*8+7];
        float mean = s * (1.0f / CH);
        float var  = q * (1.0f / CH) - mean * mean;
        sMean[tid] = mean;
        sRstd[tid] = rsqrtf(var + 1e-5f);
    }
    __syncthreads();

    // ---- normalize + relu; store bf16 OR fused linear+exp ----
    float pd[2][2] = {{0,0},{0,0}};
    #pragma unroll
    for (int mt = 0; mt < 2; mt++) {
        int r0 = wm * 32 + mt * 16 + g;
        float m0 = sMean[r0],   rs0 = sRstd[r0];
        float m1 = sMean[r0+8], rs1 = sRstd[r0+8];
        #pragma unroll
        for (int nt = 0; nt < 12; nt++) {
            int col0 = wn * 96 + nt * 8 + tg * 2;
            float ga0 = sGamma[col0], ga1 = sGamma[col0+1];
            float be0 = sBeta[col0],  be1 = sBeta[col0+1];
            float v0 = fmaxf(0.f, (c[mt][nt][0] - m0) * rs0 * ga0 + be0);
            float v1 = fmaxf(0.f, (c[mt][nt][1] - m0) * rs0 * ga1 + be1);
            float v2 = fmaxf(0.f, (c[mt][nt][2] - m1) * rs1 * ga0 + be0);
            float v3 = fmaxf(0.f, (c[mt][nt][3] - m1) * rs1 * ga1 + be1);
            if (!PRED) {
                size_t base0 = (rowBase + s0 + r0) * CH + col0;
                *(__nv_bfloat162*)(g_h1 + base0)          = __floats2bfloat162_rn(v0, v1);
                *(__nv_bfloat162*)(g_h1 + base0 + 8 * CH) = __floats2bfloat162_rn(v2, v3);
            } else {
                float w0 = sWl[col0], w1v = sWl[col0 + 1];
                pd[mt][0] += v0 * w0 + v1 * w1v;
                pd[mt][1] += v2 * w0 + v3 * w1v;
            }
        }
    }
    if (PRED) {
        #pragma unroll
        for (int mt = 0; mt < 2; mt++)
            #pragma unroll
            for (int hi = 0; hi < 2; hi++) {
                float s = pd[mt][hi];
                s += __shfl_xor_sync(0xffffffffu, s, 1);
                s += __shfl_xor_sync(0xffffffffu, s, 2);
                if (tg == 0) {
                    int r = wm * 32 + mt * 16 + g + 8 * hi;
                    sPart[r * 8 + wn] = s;
                }
            }
        __syncthreads();
        if (tid < TM) {
            float s = sPart[tid*8+0] + sPart[tid*8+1] + sPart[tid*8+2] + sPart[tid*8+3];
            pred[rowBase + s0 + tid] = expf(s + bl[0]);
        }
    }
}

// ---------------- length regulation (exact gather of fp32 x) ----------------
// warp per output row t; binary search over smem cumsum
__global__ void gather_kernel(const float* __restrict__ x, float* __restrict__ out) {
    __shared__ int sc[SEQ];
    int b = blockIdx.y;
    for (int i = threadIdx.x; i < SEQ; i += blockDim.x) sc[i] = g_cum[b * SEQ + i];
    __syncthreads();

    int warp = threadIdx.x >> 5, lane = threadIdx.x & 31;
    int t = blockIdx.x * 8 + warp;            // 0..3071
    int total = sc[SEQ - 1];
    bool valid = t < total;
    int lo = 0, hi = SEQ;
    while (lo < hi) { int mid = (lo + hi) >> 1; if (sc[mid] <= t) lo = mid + 1; else hi = mid; }
    int src = min(lo, SEQ - 1);

    const float4* xp = (const float4*)(x + ((size_t)b * SEQ + src) * CH);
    float4* op = (float4*)(out + ((size_t)b * MAXOUT + t) * CH);
    #pragma unroll
    for (int i = 0; i < 3; i++) {
        float4 v = valid ? xp[lane + 32 * i] : make_float4(0.f, 0.f, 0.f, 0.f);
        op[lane + 32 * i] = v;
    }
}

// ---------------- launch ----------------
extern "C" void kernel_launch(void* const* d_in, const int* in_sizes, int n_in,
                              void* d_out, int out_size) {
    const float* x     = (const float*)d_in[0];
    const int*   dur   = (const int*)  d_in[1];
    const float* w1    = (const float*)d_in[2];
    const float* b1    = (const float*)d_in[3];
    const float* g1    = (const float*)d_in[4];
    const float* beta1 = (const float*)d_in[5];
    const float* w2    = (const float*)d_in[6];
    const float* b2    = (const float*)d_in[7];
    const float* g2    = (const float*)d_in[8];
    const float* beta2 = (const float*)d_in[9];
    const float* wl    = (const float*)d_in[10];
    const float* bl    = (const float*)d_in[11];

    float* res  = (float*)d_out;
    float* pred = res + (size_t)BATCH * MAXOUT * CH;

    // one-time infrastructure (created on the uncaptured correctness call;
    // reused identically on every call — work per call is unchanged/deterministic)
    static cudaStream_t s_aux = nullptr;
    static cudaEvent_t  ev_fork = nullptr, ev_join = nullptr;
    static bool s_init = false;
    if (!s_init) {
        cudaStreamCreateWithFlags(&s_aux, cudaStreamNonBlocking);
        cudaEventCreateWithFlags(&ev_fork, cudaEventDisableTiming);
        cudaEventCreateWithFlags(&ev_join, cudaEventDisableTiming);
        cudaFuncSetAttribute(conv_ln_kernel<false>, cudaFuncAttributeMaxDynamicSharedMemorySize, SMEM_TOTAL);
        cudaFuncSetAttribute(conv_ln_kernel<true>,  cudaFuncAttributeMaxDynamicSharedMemorySize, SMEM_TOTAL);
        s_init = true;
    }

    // ---- fork: aux branch = cumsum -> gather (memory-bound, independent of convs) ----
    cudaEventRecord(ev_fork, 0);
    cudaStreamWaitEvent(s_aux, ev_fork, 0);
    cumsum_kernel<<<BATCH, SEQ, 0, s_aux>>>(dur);
    gather_kernel<<<dim3(MAXOUT / 8, BATCH), 256, 0, s_aux>>>(x, res);
    cudaEventRecord(ev_join, s_aux);

    // ---- main branch: prep + tensor-bound convs ----
    cvt_w_kernel<<<(CH * KTOT + 255) / 256, 256>>>(w1, 0);
    cvt_w_kernel<<<(CH * KTOT + 255) / 256, 256>>>(w2, 1);
    int n2 = ROWS * CH / 2;
    cvt_x_kernel<<<(n2 + 255) / 256, 256>>>(x, n2);

    // layer 1: conv+bias+LN+relu -> g_h1 (bf16)
    conv_ln_kernel<false><<<ROWS / TM, NTHR, SMEM_TOTAL>>>(b1, g1, beta1, nullptr, nullptr, nullptr);
    // layer 2: conv+bias+LN+relu -> @wl + bl -> exp -> pred
    conv_ln_kernel<true><<<ROWS / TM, NTHR, SMEM_TOTAL>>>(b2, g2, beta2, wl, bl, pred);

    // ---- join ----
    cudaStreamWaitEvent(0, ev_join, 0);
}